// round 1
// baseline (speedup 1.0000x reference)
#include <cuda_runtime.h>
#include <math.h>

// Problem dims
#define NB 64      // batch
#define NT 512     // time steps
#define ND 128     // input dim
#define NH 512     // hidden
#define NDS 32     // dense out
#define NG4 (4 * NH)   // 2048

// LSTM kernel config
#define NG 128         // persistent CTAs (<= 148 SMs, 1 per SM)
#define TPB 512
#define KV (NH + ND)   // 640 = concat [h ; x_t]
#define JPC (NH / NG)  // 4 hidden units per CTA
#define NCOL 16        // 4 gates * JPC z-columns per CTA
#define KCH 8          // k-split factor
#define KPT (KV / KCH) // 80 k per chunk

// Scratch (allocation-free: __device__ globals)
__device__ float g_h[2][NH][NB];      // double-buffered h, transposed [k][b]
__device__ float g_hs[NT][NH][NB];    // all hidden states, [t][j][b]
__device__ unsigned int g_bar;        // monotonic barrier counter

__global__ void init_kernel() {
    int idx = blockIdx.x * blockDim.x + threadIdx.x;
    if (idx == 0) g_bar = 0u;
    float* p = &g_h[0][0][0];
    for (int i = idx; i < NH * NB; i += gridDim.x * blockDim.x) p[i] = 0.f;
}

__device__ __forceinline__ float sigmoidf_(float x) { return 1.f / (1.f + expf(-x)); }

__global__ void __launch_bounds__(TPB, 1) lstm_kernel(
    const float* __restrict__ x,      // [NB][NT][ND]
    const float* __restrict__ wk,     // [ND][4H]
    const float* __restrict__ wr,     // [NH][4H]
    const float* __restrict__ bias,   // [4H]
    float* __restrict__ out_h,        // [NB][NH]
    float* __restrict__ out_c)        // [NB][NH]
{
    extern __shared__ float smem[];
    float* Ws  = smem;                  // [KV][NCOL]  40 KB, resident all steps
    float* v   = smem + KV * NCOL;      // [KV][NB]    160 KB, per-step [h;x_t]^T
    float* red = v;                     // alias after compute: [NCOL][KCH][NB]

    const int tid = threadIdx.x;
    const int j0 = blockIdx.x * JPC;

    // One-time: load this CTA's weight slice (16 gate-columns, K=640)
    for (int i = tid; i < KV * NCOL; i += TPB) {
        int k = i / NCOL, c16 = i % NCOL;
        int gate = c16 >> 2, jj = c16 & 3;
        int col = gate * NH + j0 + jj;
        Ws[i] = (k < NH) ? wr[(size_t)k * NG4 + col]
                         : wk[(size_t)(k - NH) * NG4 + col];
    }

    // Gate-thread (tid < 256) persistent state: one (b, jj) pair each
    const int gb = tid & 63;
    const int gj = (tid >> 6) & 3;
    float c_state = 0.f;
    float bz[4] = {0.f, 0.f, 0.f, 0.f};
    if (tid < 256) {
        #pragma unroll
        for (int gg = 0; gg < 4; gg++) bz[gg] = bias[gg * NH + j0 + gj];
    }

    // Compute-thread tiling: (kc, bg, cg) -> 4 batches x 4 cols x K/8
    const int kc  = tid >> 6;      // 0..7
    const int rem = tid & 63;
    const int cg  = rem & 3;       // 4 col-groups of 4
    const int bg  = rem >> 2;      // 16 batch-groups of 4
    const int k0  = kc * KPT;

    for (int t = 0; t < NT; t++) {
        // ---- Broadcast load: v = [h_{t-1} ; x_t] transposed into SMEM ----
        {
            const float4* src = reinterpret_cast<const float4*>(&g_h[t & 1][0][0]);
            float4* dst = reinterpret_cast<float4*>(v);
            #pragma unroll 4
            for (int i = tid; i < (NH * NB) / 4; i += TPB)
                dst[i] = __ldcg(src + i);   // bypass L1 (cross-CTA producer)
        }
        for (int i = tid; i < (ND / 4) * NB; i += TPB) {
            int b = i & 63, kq = i >> 6;
            float4 xv = *reinterpret_cast<const float4*>(
                x + (size_t)b * NT * ND + (size_t)t * ND + kq * 4);
            int kb = (NH + kq * 4) * NB + b;
            v[kb]          = xv.x;
            v[kb + NB]     = xv.y;
            v[kb + 2 * NB] = xv.z;
            v[kb + 3 * NB] = xv.w;
        }
        __syncthreads();

        // ---- z partials: 4x4 register tile over k-chunk ----
        float acc[4][4];
        #pragma unroll
        for (int bi = 0; bi < 4; bi++)
            #pragma unroll
            for (int ci = 0; ci < 4; ci++) acc[bi][ci] = 0.f;

        const float* vp = v  + (size_t)k0 * NB   + bg * 4;
        const float* wp = Ws + (size_t)k0 * NCOL + cg * 4;
        #pragma unroll 4
        for (int k = 0; k < KPT; k++) {
            float4 hv = *reinterpret_cast<const float4*>(vp + (size_t)k * NB);
            float4 wv = *reinterpret_cast<const float4*>(wp + (size_t)k * NCOL);
            float hvv[4] = {hv.x, hv.y, hv.z, hv.w};
            float wvv[4] = {wv.x, wv.y, wv.z, wv.w};
            #pragma unroll
            for (int bi = 0; bi < 4; bi++)
                #pragma unroll
                for (int ci = 0; ci < 4; ci++)
                    acc[bi][ci] += hvv[bi] * wvv[ci];
        }
        __syncthreads();   // v no longer needed; safe to alias as red

        // ---- store partials: red[c][kc][b] ----
        #pragma unroll
        for (int ci = 0; ci < 4; ci++) {
            float4 sv = make_float4(acc[0][ci], acc[1][ci], acc[2][ci], acc[3][ci]);
            *reinterpret_cast<float4*>(
                &red[((size_t)(cg * 4 + ci) * KCH + kc) * NB + bg * 4]) = sv;
        }
        __syncthreads();

        // ---- gates + state update (256 threads: one (b, jj) each) ----
        if (tid < 256) {
            float z[4];
            #pragma unroll
            for (int gg = 0; gg < 4; gg++) {
                float s = bz[gg];
                #pragma unroll
                for (int kk = 0; kk < KCH; kk++)
                    s += red[((size_t)(gg * 4 + gj) * KCH + kk) * NB + gb];
                z[gg] = s;
            }
            float ig = sigmoidf_(z[0]);
            float fg = sigmoidf_(z[1]);
            float gv = tanhf(z[2]);
            float og = sigmoidf_(z[3]);
            c_state = fg * c_state + ig * gv;
            float hv = og * tanhf(c_state);
            int row = j0 + gj;
            g_h[(t + 1) & 1][row][gb] = hv;
            g_hs[t][row][gb] = hv;
            if (t == NT - 1) {
                out_h[(size_t)gb * NH + row] = hv;
                out_c[(size_t)gb * NH + row] = c_state;
            }
        }
        __syncthreads();

        // ---- grid barrier (monotonic counter; all 128 CTAs co-resident) ----
        if (tid == 0) {
            __threadfence();
            atomicAdd(&g_bar, 1u);
            unsigned int target = (unsigned int)NG * (unsigned int)(t + 1);
            unsigned int cur;
            do {
                asm volatile("ld.volatile.global.u32 %0, [%1];"
                             : "=r"(cur) : "l"(&g_bar));
            } while (cur < target);
            __threadfence();
        }
        __syncthreads();
    }
}

// ---- Dense(32, tanh) over all timesteps ----
#define DTPB 256
__global__ void __launch_bounds__(DTPB, 1) dense_kernel(
    const float* __restrict__ dw,   // [NH][NDS]
    const float* __restrict__ db,   // [NDS]
    float* __restrict__ out)        // [NB][NT][NDS]
{
    extern __shared__ float smem[];
    float* hsm = smem;              // [NH][NB]  128 KB
    float* wsm = smem + NH * NB;    // [NH][NDS]  64 KB
    int t = blockIdx.x, tid = threadIdx.x;
    {
        const float4* src = reinterpret_cast<const float4*>(&g_hs[t][0][0]);
        float4* dst = reinterpret_cast<float4*>(hsm);
        for (int i = tid; i < NH * NB / 4; i += DTPB) dst[i] = src[i];
        const float4* ws = reinterpret_cast<const float4*>(dw);
        float4* wd = reinterpret_cast<float4*>(wsm);
        for (int i = tid; i < NH * NDS / 4; i += DTPB) wd[i] = ws[i];
    }
    __syncthreads();

    int bg = tid & 15;   // 4 batches each
    int dg = tid >> 4;   // 2 dense cols each
    float acc[4][2];
    #pragma unroll
    for (int bi = 0; bi < 4; bi++) { acc[bi][0] = 0.f; acc[bi][1] = 0.f; }

    #pragma unroll 4
    for (int k = 0; k < NH; k++) {
        float4 hv = *reinterpret_cast<const float4*>(&hsm[k * NB + bg * 4]);
        float2 wv = *reinterpret_cast<const float2*>(&wsm[k * NDS + dg * 2]);
        float hvv[4] = {hv.x, hv.y, hv.z, hv.w};
        #pragma unroll
        for (int bi = 0; bi < 4; bi++) {
            acc[bi][0] += hvv[bi] * wv.x;
            acc[bi][1] += hvv[bi] * wv.y;
        }
    }
    float b0 = db[dg * 2], b1 = db[dg * 2 + 1];
    #pragma unroll
    for (int bi = 0; bi < 4; bi++) {
        int b = bg * 4 + bi;
        size_t base = (size_t)b * NT * NDS + (size_t)t * NDS + dg * 2;
        out[base]     = tanhf(acc[bi][0] + b0);
        out[base + 1] = tanhf(acc[bi][1] + b1);
    }
}

#define LSTM_SMEM ((KV * NCOL + KV * NB) * 4)         // 204800 B
#define DENSE_SMEM ((NH * NB + NH * NDS) * 4)         // 196608 B

extern "C" void kernel_launch(void* const* d_in, const int* in_sizes, int n_in,
                              void* d_out, int out_size) {
    const float* x    = (const float*)d_in[0];
    const float* wk   = (const float*)d_in[1];
    const float* wr   = (const float*)d_in[2];
    const float* bias = (const float*)d_in[3];
    const float* dw   = (const float*)d_in[4];
    const float* db   = (const float*)d_in[5];
    float* out   = (float*)d_out;                         // [NB][NT][NDS]
    float* out_h = out + (size_t)NB * NT * NDS;           // [NB][NH]
    float* out_c = out_h + (size_t)NB * NH;               // [NB][NH]

    cudaFuncSetAttribute(lstm_kernel,
                         cudaFuncAttributeMaxDynamicSharedMemorySize, LSTM_SMEM);
    cudaFuncSetAttribute(dense_kernel,
                         cudaFuncAttributeMaxDynamicSharedMemorySize, DENSE_SMEM);

    init_kernel<<<64, 256>>>();
    lstm_kernel<<<NG, TPB, LSTM_SMEM>>>(x, wk, wr, bias, out_h, out_c);
    dense_kernel<<<NT, DTPB, DENSE_SMEM>>>(dw, db, out);
}

// round 3
// speedup vs baseline: 1.1394x; 1.1394x over previous
#include <cuda_runtime.h>
#include <cuda_bf16.h>
#include <cstdint>
#include <math.h>

// ---------------- problem dims ----------------
#define NB 64
#define NT 512
#define ND 128
#define NH 512
#define NDS 32
#define NG4 (4 * NH)   // 2048

// ---------------- LSTM kernel config ----------------
#define G 128          // persistent CTAs, 1/SM
#define TPB 256        // 8 warps
#define JPC 4          // hidden units per CTA
#define KTOT 640       // K = NH + ND
#define NKS 40         // k-steps of 16
#define NCH 80         // 16B chunks per row (640*2/16)
#define ROWB 1280      // bytes per SMEM row

// SMEM layout (bytes)
#define A_OFF 0                    // [128][1280]  163840
#define B_OFF 163840               // [32][1280]    40960
#define ZB_OFF 204800              // [128][33] f32 16896
#define LSTM_SMEM 221696

__device__ __forceinline__ uint32_t smem_u32(const void* p) {
    uint32_t a;
    asm("{ .reg .u64 t; cvta.to.shared.u64 t, %1; cvt.u32.u64 %0, t; }" : "=r"(a) : "l"(p));
    return a;
}
__device__ __forceinline__ uint16_t bf16_bits(float f) {
    return __bfloat16_as_ushort(__float2bfloat16(f));
}
__device__ __forceinline__ float bf16_val(float f) {
    return __bfloat162float(__float2bfloat16(f));
}
__device__ __forceinline__ float sigmoidf_(float x) { return 1.f / (1.f + expf(-x)); }

__device__ __forceinline__ uint4 pack_hi8(float4 a, float4 b) {
    uint4 r;
    r.x = (uint32_t)bf16_bits(a.x) | ((uint32_t)bf16_bits(a.y) << 16);
    r.y = (uint32_t)bf16_bits(a.z) | ((uint32_t)bf16_bits(a.w) << 16);
    r.z = (uint32_t)bf16_bits(b.x) | ((uint32_t)bf16_bits(b.y) << 16);
    r.w = (uint32_t)bf16_bits(b.z) | ((uint32_t)bf16_bits(b.w) << 16);
    return r;
}
__device__ __forceinline__ uint16_t bf16_lo(float f) {
    return bf16_bits(f - bf16_val(f));
}
__device__ __forceinline__ uint4 pack_lo8(float4 a, float4 b) {
    uint4 r;
    r.x = (uint32_t)bf16_lo(a.x) | ((uint32_t)bf16_lo(a.y) << 16);
    r.y = (uint32_t)bf16_lo(a.z) | ((uint32_t)bf16_lo(a.w) << 16);
    r.z = (uint32_t)bf16_lo(b.x) | ((uint32_t)bf16_lo(b.y) << 16);
    r.w = (uint32_t)bf16_lo(b.z) | ((uint32_t)bf16_lo(b.w) << 16);
    return r;
}

#define LDSM_X4(r0, r1, r2, r3, addr) \
    asm volatile("ldmatrix.sync.aligned.m8n8.x4.shared.b16 {%0,%1,%2,%3}, [%4];" \
        : "=r"(r0), "=r"(r1), "=r"(r2), "=r"(r3) : "r"(addr))

#define MMA_BF16(c, a0, a1, a2, a3, b0, b1) \
    asm volatile("mma.sync.aligned.m16n8k16.row.col.f32.bf16.bf16.f32 " \
        "{%0,%1,%2,%3}, {%4,%5,%6,%7}, {%8,%9}, {%0,%1,%2,%3};" \
        : "+f"((c)[0]), "+f"((c)[1]), "+f"((c)[2]), "+f"((c)[3]) \
        : "r"(a0), "r"(a1), "r"(a2), "r"(a3), "r"(b0), "r"(b1))

// ---------------- global scratch ----------------
__device__ __nv_bfloat16 g_hh[NB][NH];   // h hi
__device__ __nv_bfloat16 g_hl[NB][NH];   // h lo
__device__ float g_hs[NT][NH][NB];       // hidden states for dense (64 MB)
__device__ unsigned int g_bar;

__global__ void init_kernel() {
    int idx = blockIdx.x * blockDim.x + threadIdx.x;
    if (idx == 0) g_bar = 0u;
    uint32_t* ph = reinterpret_cast<uint32_t*>(&g_hh[0][0]);
    uint32_t* pl = reinterpret_cast<uint32_t*>(&g_hl[0][0]);
    for (int i = idx; i < NB * NH / 2; i += gridDim.x * blockDim.x) {
        ph[i] = 0u; pl[i] = 0u;
    }
}

// =====================================================================
// Persistent LSTM recurrence, warp-level bf16 HMMA with hi/lo split.
// CTA g owns hidden units [4g, 4g+4) -> 16 true z-cols -> 32 B' rows.
// =====================================================================
__global__ void __launch_bounds__(TPB, 1) lstm_kernel(
    const float* __restrict__ x,      // [NB][NT][ND]
    const float* __restrict__ wk,     // [ND][4H]
    const float* __restrict__ wr,     // [NH][4H]
    const float* __restrict__ bias,   // [4H]
    float* __restrict__ out_h, float* __restrict__ out_c)
{
    extern __shared__ char smem[];
    const uint32_t sbu = smem_u32(smem);
    float* zb = reinterpret_cast<float*>(smem + ZB_OFF);   // [128][33]

    const int tid = threadIdx.x;
    const int wid = tid >> 5, lane = tid & 31;
    const int j0 = blockIdx.x * JPC;

    // ---- B' once: rows 0-15 = hi of local col, rows 16-31 = lo ----
    for (int i = tid; i < 32 * KTOT; i += TPB) {
        int n = i & 31, k = i >> 5;
        int c = n & 15, gate = c >> 2, jj = c & 3;
        int col = gate * NH + j0 + jj;
        float w = (k < NH) ? wr[(size_t)k * NG4 + col]
                           : wk[(size_t)(k - NH) * NG4 + col];
        uint16_t bv = (n < 16) ? bf16_bits(w) : bf16_lo(w);
        *reinterpret_cast<uint16_t*>(smem + B_OFF + n * ROWB +
            ((((k >> 3) ^ (n & 7)) << 4) | ((k & 7) << 1))) = bv;
    }

    // gate-thread identity: one (batch, local-j) pair per thread
    const int gb = tid & 63;
    const int gj = (tid >> 6) & 3;
    float c_state = 0.f;
    float bz[4];
    #pragma unroll
    for (int g = 0; g < 4; g++) bz[g] = bias[g * NH + j0 + gj];

    // ldmatrix per-lane row bases (swizzle xor s = lane&7 for both A and B)
    const int s7 = lane & 7;
    const int arow = wid * 16 + ((lane >> 3) & 1) * 8 + s7;
    const uint32_t abase = sbu + A_OFF + arow * ROWB;
    const int acb = lane >> 4;                 // A chunk bit
    const int brow = ((lane >> 4) << 3) + s7;
    const uint32_t bbase = sbu + B_OFF + brow * ROWB;
    const int bcb = (lane >> 3) & 1;           // B chunk bit

    __syncthreads();

    for (int t = 0; t < NT; t++) {
        // ---- populate A: rows 0-63 hi / 64-127 lo, k = [h(512) ; x_t(128)] ----
        // h-part: 256 (row, half) segments, 32 coalesced 16B chunks each
        #pragma unroll 4
        for (int seg = wid; seg < 256; seg += 8) {
            int row = seg >> 1;
            int cs = ((seg & 1) << 5) + lane;          // chunk 0..63
            const uint4* src = (row < 64)
                ? reinterpret_cast<const uint4*>(&g_hh[row][0])
                : reinterpret_cast<const uint4*>(&g_hl[row - 64][0]);
            uint4 v = __ldcg(src + cs);
            *reinterpret_cast<uint4*>(smem + row * ROWB +
                ((cs ^ (row & 7)) << 4)) = v;
        }
        // x-part: chunks 64..79, converted fp32 -> bf16 hi/lo
        #pragma unroll
        for (int i = tid; i < 128 * 16; i += TPB) {
            int row = i >> 4, c = i & 15;
            int b = row & 63, d0 = c * 8;
            const float4* xp = reinterpret_cast<const float4*>(
                x + ((size_t)b * NT + t) * ND + d0);
            float4 x0 = xp[0], x1 = xp[1];
            uint4 v = (row < 64) ? pack_hi8(x0, x1) : pack_lo8(x0, x1);
            *reinterpret_cast<uint4*>(smem + row * ROWB +
                (((c + 64) ^ (row & 7)) << 4)) = v;
        }
        __syncthreads();

        // ---- MMA: warp wid owns M-tile [wid*16, wid*16+16), all 4 N-tiles ----
        float acc[4][4];
        #pragma unroll
        for (int nt = 0; nt < 4; nt++)
            #pragma unroll
            for (int q = 0; q < 4; q++) acc[nt][q] = 0.f;

        #pragma unroll 4
        for (int ks = 0; ks < NKS; ks++) {
            uint32_t a0, a1, a2, a3;
            uint32_t aaddr = abase + (((ks * 2 + acb) ^ s7) << 4);
            LDSM_X4(a0, a1, a2, a3, aaddr);
            uint32_t b00, b01, b10, b11, b20, b21, b30, b31;
            uint32_t baddr = bbase + (((ks * 2 + bcb) ^ s7) << 4);
            LDSM_X4(b00, b01, b10, b11, baddr);
            LDSM_X4(b20, b21, b30, b31, baddr + 16 * ROWB);
            MMA_BF16(acc[0], a0, a1, a2, a3, b00, b01);
            MMA_BF16(acc[1], a0, a1, a2, a3, b10, b11);
            MMA_BF16(acc[2], a0, a1, a2, a3, b20, b21);
            MMA_BF16(acc[3], a0, a1, a2, a3, b30, b31);
        }

        // ---- epilogue: accums -> zb[128][33] ----
        {
            int r0 = wid * 16 + (lane >> 2);
            int cc = (lane & 3) * 2;
            #pragma unroll
            for (int nt = 0; nt < 4; nt++) {
                int col = nt * 8 + cc;
                zb[r0 * 33 + col]           = acc[nt][0];
                zb[r0 * 33 + col + 1]       = acc[nt][1];
                zb[(r0 + 8) * 33 + col]     = acc[nt][2];
                zb[(r0 + 8) * 33 + col + 1] = acc[nt][3];
            }
        }
        __syncthreads();

        // ---- gates: z = bias + hi_row + lo_row, hi_col + lo_col partials ----
        {
            float z[4];
            #pragma unroll
            for (int g = 0; g < 4; g++) {
                int n = g * 4 + gj;
                z[g] = bz[g]
                     + zb[gb * 33 + n]        + zb[(gb + 64) * 33 + n]
                     + zb[gb * 33 + n + 16]   + zb[(gb + 64) * 33 + n + 16];
            }
            float ig = sigmoidf_(z[0]);
            float fg = sigmoidf_(z[1]);
            float gv = tanhf(z[2]);
            float og = sigmoidf_(z[3]);
            c_state = fg * c_state + ig * gv;
            float hv = og * tanhf(c_state);
            int row = j0 + gj;
            __nv_bfloat16 hh = __float2bfloat16(hv);
            g_hh[gb][row] = hh;
            g_hl[gb][row] = __float2bfloat16(hv - __bfloat162float(hh));
            g_hs[t][row][gb] = hv;
            if (t == NT - 1) {
                out_h[(size_t)gb * NH + row] = hv;
                out_c[(size_t)gb * NH + row] = c_state;
            }
        }
        __syncthreads();

        // ---- grid barrier (128 co-resident CTAs, monotonic counter) ----
        if (tid == 0) {
            __threadfence();
            atomicAdd(&g_bar, 1u);
            unsigned int target = (unsigned int)G * (unsigned int)(t + 1);
            unsigned int cur;
            do {
                asm volatile("ld.volatile.global.u32 %0, [%1];" : "=r"(cur) : "l"(&g_bar));
            } while (cur < target);
            __threadfence();
        }
        __syncthreads();
    }
}

// ---------------- Dense(32, tanh) over all timesteps ----------------
#define DTPB 256
__global__ void __launch_bounds__(DTPB, 1) dense_kernel(
    const float* __restrict__ dw, const float* __restrict__ db,
    float* __restrict__ out)
{
    extern __shared__ float smemf[];
    float* hsm = smemf;
    float* wsm = smemf + NH * NB;
    int t = blockIdx.x, tid = threadIdx.x;
    {
        const float4* src = reinterpret_cast<const float4*>(&g_hs[t][0][0]);
        float4* dst = reinterpret_cast<float4*>(hsm);
        for (int i = tid; i < NH * NB / 4; i += DTPB) dst[i] = src[i];
        const float4* ws = reinterpret_cast<const float4*>(dw);
        float4* wd = reinterpret_cast<float4*>(wsm);
        for (int i = tid; i < NH * NDS / 4; i += DTPB) wd[i] = ws[i];
    }
    __syncthreads();

    int bg = tid & 15, dg = tid >> 4;
    float acc[4][2];
    #pragma unroll
    for (int bi = 0; bi < 4; bi++) { acc[bi][0] = 0.f; acc[bi][1] = 0.f; }
    #pragma unroll 4
    for (int k = 0; k < NH; k++) {
        float4 hv = *reinterpret_cast<const float4*>(&hsm[k * NB + bg * 4]);
        float2 wv = *reinterpret_cast<const float2*>(&wsm[k * NDS + dg * 2]);
        float hvv[4] = {hv.x, hv.y, hv.z, hv.w};
        #pragma unroll
        for (int bi = 0; bi < 4; bi++) {
            acc[bi][0] += hvv[bi] * wv.x;
            acc[bi][1] += hvv[bi] * wv.y;
        }
    }
    float b0 = db[dg * 2], b1 = db[dg * 2 + 1];
    #pragma unroll
    for (int bi = 0; bi < 4; bi++) {
        int b = bg * 4 + bi;
        size_t base = (size_t)b * NT * NDS + (size_t)t * NDS + dg * 2;
        out[base]     = tanhf(acc[bi][0] + b0);
        out[base + 1] = tanhf(acc[bi][1] + b1);
    }
}

#define DENSE_SMEM ((NH * NB + NH * NDS) * 4)

extern "C" void kernel_launch(void* const* d_in, const int* in_sizes, int n_in,
                              void* d_out, int out_size) {
    const float* x    = (const float*)d_in[0];
    const float* wk   = (const float*)d_in[1];
    const float* wr   = (const float*)d_in[2];
    const float* bias = (const float*)d_in[3];
    const float* dw   = (const float*)d_in[4];
    const float* db   = (const float*)d_in[5];
    float* out   = (float*)d_out;
    float* out_h = out + (size_t)NB * NT * NDS;
    float* out_c = out_h + (size_t)NB * NH;

    cudaFuncSetAttribute(lstm_kernel,
                         cudaFuncAttributeMaxDynamicSharedMemorySize, LSTM_SMEM);
    cudaFuncSetAttribute(dense_kernel,
                         cudaFuncAttributeMaxDynamicSharedMemorySize, DENSE_SMEM);

    init_kernel<<<64, 256>>>();
    lstm_kernel<<<G, TPB, LSTM_SMEM>>>(x, wk, wr, bias, out_h, out_c);
    dense_kernel<<<NT, DTPB, DENSE_SMEM>>>(dw, db, out);
}